// round 2
// baseline (speedup 1.0000x reference)
#include <cuda_runtime.h>
#include <cuda_bf16.h>

// Problem constants (fixed by the dataset):
//   x      : [4, 2048, 4096] fp32  -> M = 8192, K = 4096
//   weight : [4096, 4096]    fp32  -> N = 4096 (row-major, K contiguous)
//   bias   : [4096]          fp32
//   out    : [4, 2048, 4096] fp32
#define DK 4096
#define DN 4096
#define GROUP 128
#define EPSQ 1e-8f

// Scratch for fake-quantized weight (allocation-free rule: __device__ global).
__device__ float g_wq[(size_t)DN * DK];

// ---------------------------------------------------------------------------
// Kernel 1: per-group (128 contiguous elements over flattened weight) min/max
// INT2 fake quantization. One warp per group; lane holds 4 elements.
// Matches reference math: scale = rng/3, q = clip(rint((x-mn)/scale),0,3),
// deq = q*scale + mn, pass-through when rng < 1e-8.
// ---------------------------------------------------------------------------
__global__ __launch_bounds__(256) void quant_kernel(const float* __restrict__ w) {
    const int warp = threadIdx.x >> 5;
    const int lane = threadIdx.x & 31;
    const long g = (long)blockIdx.x * 8 + warp;           // group index
    const float* p = w + g * GROUP;

    float v[4];
    float mn =  INFINITY;
    float mx = -INFINITY;
#pragma unroll
    for (int i = 0; i < 4; i++) {
        v[i] = p[lane + 32 * i];
        mn = fminf(mn, v[i]);
        mx = fmaxf(mx, v[i]);
    }
#pragma unroll
    for (int o = 16; o > 0; o >>= 1) {
        mn = fminf(mn, __shfl_xor_sync(0xffffffffu, mn, o));
        mx = fmaxf(mx, __shfl_xor_sync(0xffffffffu, mx, o));
    }

    const float rng = mx - mn;
    const bool passthrough = rng < EPSQ;
    const float scale = rng * (1.0f / 3.0f);
    const float safe_scale = passthrough ? 1.0f : scale;

    float* q_out = g_wq + g * GROUP;
#pragma unroll
    for (int i = 0; i < 4; i++) {
        float q = rintf((v[i] - mn) / safe_scale);   // round-half-even, like jnp.round
        q = fminf(fmaxf(q, 0.0f), 3.0f);
        const float deq = q * scale + mn;
        q_out[lane + 32 * i] = passthrough ? v[i] : deq;
    }
}

// ---------------------------------------------------------------------------
// Kernel 2: fp32 NT-GEMM  C[M,N] = X[M,K] * Wq[N,K]^T + bias
// 128x128 block tile, BK=16, 256 threads, 8x8 per-thread micro-tile.
// ---------------------------------------------------------------------------
constexpr int BM = 128;
constexpr int BN = 128;
constexpr int BK = 16;
constexpr int TM = 8;
constexpr int TN = 8;

__global__ __launch_bounds__(256, 2) void gemm_kernel(
    const float* __restrict__ X,
    const float* __restrict__ bias,
    float* __restrict__ C) {

    __shared__ float Xs[BK][BM + 4];
    __shared__ float Ws[BK][BN + 4];

    const float* __restrict__ W = g_wq;

    const int tid = threadIdx.x;
    const int bn = blockIdx.x * BN;
    const int bm = blockIdx.y * BM;
    const int tx = tid & 15;     // 16 cols of threads
    const int ty = tid >> 4;     // 16 rows of threads

    float acc[TM][TN];
#pragma unroll
    for (int i = 0; i < TM; i++)
#pragma unroll
        for (int j = 0; j < TN; j++) acc[i][j] = 0.0f;

    for (int k0 = 0; k0 < DK; k0 += BK) {
        // Load 128x16 tiles of X and Wq. 512 float4 each, 2 per thread.
#pragma unroll
        for (int r = 0; r < 2; r++) {
            const int q   = tid + r * 256;
            const int row = q >> 2;            // 0..127
            const int kq  = (q & 3) * 4;       // 0,4,8,12

            float4 xv = *(const float4*)(X + (long)(bm + row) * DK + k0 + kq);
            Xs[kq + 0][row] = xv.x;
            Xs[kq + 1][row] = xv.y;
            Xs[kq + 2][row] = xv.z;
            Xs[kq + 3][row] = xv.w;

            float4 wv = *(const float4*)(W + (long)(bn + row) * DK + k0 + kq);
            Ws[kq + 0][row] = wv.x;
            Ws[kq + 1][row] = wv.y;
            Ws[kq + 2][row] = wv.z;
            Ws[kq + 3][row] = wv.w;
        }
        __syncthreads();

#pragma unroll
        for (int kk = 0; kk < BK; kk++) {
            float a[TM], b[TN];
#pragma unroll
            for (int i = 0; i < TM; i++) a[i] = Xs[kk][ty * TM + i];
#pragma unroll
            for (int j = 0; j < TN; j++) b[j] = Ws[kk][tx * TN + j];
#pragma unroll
            for (int i = 0; i < TM; i++)
#pragma unroll
                for (int j = 0; j < TN; j++) acc[i][j] = fmaf(a[i], b[j], acc[i][j]);
        }
        __syncthreads();
    }

    // Epilogue: add bias, store with float4.
#pragma unroll
    for (int i = 0; i < TM; i++) {
        const long row = bm + ty * TM + i;
        float* cp = C + row * DN + bn + tx * TN;
#pragma unroll
        for (int j4 = 0; j4 < TN; j4 += 4) {
            float4 o;
            o.x = acc[i][j4 + 0] + bias[bn + tx * TN + j4 + 0];
            o.y = acc[i][j4 + 1] + bias[bn + tx * TN + j4 + 1];
            o.z = acc[i][j4 + 2] + bias[bn + tx * TN + j4 + 2];
            o.w = acc[i][j4 + 3] + bias[bn + tx * TN + j4 + 3];
            *(float4*)(cp + j4) = o;
        }
    }
}

// ---------------------------------------------------------------------------
extern "C" void kernel_launch(void* const* d_in, const int* in_sizes, int n_in,
                              void* d_out, int out_size) {
    const float* x    = (const float*)d_in[0];   // [M, K]
    const float* w    = (const float*)d_in[1];   // [N, K]
    const float* bias = (const float*)d_in[2];   // [N]
    float* out = (float*)d_out;                  // [M, N]

    const int M = out_size / DN;                 // 8192

    // 131072 groups, 8 per block (one warp each)
    const int n_groups = (DN * DK) / GROUP;
    quant_kernel<<<n_groups / 8, 256>>>(w);

    dim3 grid(DN / BN, M / BM);
    gemm_kernel<<<grid, 256>>>(x, bias, out);
}

// round 4
// speedup vs baseline: 2.7283x; 2.7283x over previous
#include <cuda_runtime.h>
#include <cuda_bf16.h>
#include <cstdint>

#define DK 4096
#define DN 4096
#define GROUP 128
#define EPSQ 1e-8f

#define BM 128
#define BN 128
#define BKE 64                 // K elements per stage (64 bf16 = 128B rows)
#define NSTAGES (DK / BKE)

// ---------------- device scratch (allocation-free rule) ----------------
__device__ __nv_bfloat16 g_whi[(size_t)DN * DK];
__device__ __nv_bfloat16 g_wlo[(size_t)DN * DK];
__device__ __nv_bfloat16 g_xhi[(size_t)8192 * DK];
__device__ __nv_bfloat16 g_xlo[(size_t)8192 * DK];

// ---------------- PTX helpers (all baseline sm_80+ ISA) ----------------
__device__ __forceinline__ uint32_t smem_u32(const void* p) {
    uint32_t a;
    asm("{ .reg .u64 t; cvta.to.shared.u64 t, %1; cvt.u32.u64 %0, t; }" : "=r"(a) : "l"(p));
    return a;
}
__device__ __forceinline__ uint32_t swz128(uint32_t off) {
    return off ^ ((off >> 3) & 0x70);
}
__device__ __forceinline__ void cp_async16(uint32_t saddr, const void* gaddr) {
    asm volatile("cp.async.cg.shared.global [%0], [%1], 16;" :: "r"(saddr), "l"(gaddr) : "memory");
}
__device__ __forceinline__ void cp_commit() {
    asm volatile("cp.async.commit_group;" ::: "memory");
}
template <int N>
__device__ __forceinline__ void cp_wait() {
    asm volatile("cp.async.wait_group %0;" :: "n"(N) : "memory");
}
__device__ __forceinline__ void ldsm4(uint32_t* r, uint32_t addr) {
    asm volatile("ldmatrix.sync.aligned.m8n8.x4.shared.b16 {%0,%1,%2,%3}, [%4];"
                 : "=r"(r[0]), "=r"(r[1]), "=r"(r[2]), "=r"(r[3]) : "r"(addr));
}
__device__ __forceinline__ void mma16816(float* d, const uint32_t* a, uint32_t b0, uint32_t b1) {
    asm volatile(
        "mma.sync.aligned.m16n8k16.row.col.f32.bf16.bf16.f32 "
        "{%0,%1,%2,%3}, {%4,%5,%6,%7}, {%8,%9}, {%0,%1,%2,%3};"
        : "+f"(d[0]), "+f"(d[1]), "+f"(d[2]), "+f"(d[3])
        : "r"(a[0]), "r"(a[1]), "r"(a[2]), "r"(a[3]), "r"(b0), "r"(b1));
}

// ---------------- Kernel 1: fake-quant + bf16 hi/lo split of W ----------------
__global__ __launch_bounds__(256) void quant_kernel(const float* __restrict__ w) {
    const int warp = threadIdx.x >> 5;
    const int lane = threadIdx.x & 31;
    const long g = (long)blockIdx.x * 8 + warp;
    const float* p = w + g * GROUP;

    float v[4];
    float mn = INFINITY, mx = -INFINITY;
#pragma unroll
    for (int i = 0; i < 4; i++) {
        v[i] = p[lane + 32 * i];
        mn = fminf(mn, v[i]);
        mx = fmaxf(mx, v[i]);
    }
#pragma unroll
    for (int o = 16; o > 0; o >>= 1) {
        mn = fminf(mn, __shfl_xor_sync(0xffffffffu, mn, o));
        mx = fmaxf(mx, __shfl_xor_sync(0xffffffffu, mx, o));
    }
    const float rng = mx - mn;
    const bool pass = rng < EPSQ;
    const float scale = rng * (1.0f / 3.0f);
    const float sscale = pass ? 1.0f : scale;

#pragma unroll
    for (int i = 0; i < 4; i++) {
        float q = rintf((v[i] - mn) / sscale);
        q = fminf(fmaxf(q, 0.0f), 3.0f);
        float deq = pass ? v[i] : (q * scale + mn);
        __nv_bfloat16 hi = __float2bfloat16(deq);
        __nv_bfloat16 lo = __float2bfloat16(deq - __bfloat162float(hi));
        g_whi[g * GROUP + lane + 32 * i] = hi;
        g_wlo[g * GROUP + lane + 32 * i] = lo;
    }
}

// ---------------- Kernel 2: bf16 hi/lo split of X ----------------
__global__ __launch_bounds__(1024) void xsplit_kernel(const float* __restrict__ x) {
    const size_t i4 = (size_t)blockIdx.x * 1024 + threadIdx.x;
    float4 v = ((const float4*)x)[i4];
    __nv_bfloat16 h[4], l[4];
    float f[4] = {v.x, v.y, v.z, v.w};
#pragma unroll
    for (int j = 0; j < 4; j++) {
        h[j] = __float2bfloat16(f[j]);
        l[j] = __float2bfloat16(f[j] - __bfloat162float(h[j]));
    }
    *(uint2*)&g_xhi[i4 * 4] = *(uint2*)h;
    *(uint2*)&g_xlo[i4 * 4] = *(uint2*)l;
}

// ---------------- Kernel 3: mma.sync bf16 GEMM ----------------
// SMEM: 2 stages x 4 buffers (Ahi, Alo, Bhi, Blo), each 128x64 bf16 = 16KB.
#define BUF_BYTES (128 * 128)          // 128 rows x 128B
#define STAGE_BYTES (4 * BUF_BYTES)    // 64KB
#define SM_TOTAL (2 * STAGE_BYTES)     // 128KB

__global__ __launch_bounds__(256) void gemm_kernel(
    const float* __restrict__ bias, float* __restrict__ C) {

    extern __shared__ char sm[];
    const uint32_t sbase = smem_u32(sm);

    const int tid = threadIdx.x;
    const int wid = tid >> 5;
    const int lane = tid & 31;
    const int wm = wid >> 1;          // 0..3  -> warp rows  [wm*32, +32)
    const int wn = wid & 1;           // 0..1  -> warp cols  [wn*64, +64)
    const int bn = blockIdx.x * BN;
    const int bm = blockIdx.y * BM;

    const __nv_bfloat16* __restrict__ Xh = g_xhi;
    const __nv_bfloat16* __restrict__ Xl = g_xlo;
    const __nv_bfloat16* __restrict__ Wh = g_whi;
    const __nv_bfloat16* __restrict__ Wl = g_wlo;

    // per-thread load mapping: idx = tid + it*256 in [0,1024): row=idx>>3, chunk=idx&7
    const int lrow = tid >> 3;            // advances by 32 per iteration
    const int lchk = tid & 7;
    const uint32_t lso = swz128(lrow * 128 + lchk * 16);   // swizzle invariant to row+=32
    const size_t lgo = (size_t)lrow * DK + lchk * 8;

    // stage loader
    auto load_stage = [&](int s, int buf) {
        const int k0 = s * BKE;
        const uint32_t st = sbase + buf * STAGE_BYTES;
#pragma unroll
        for (int it = 0; it < 4; it++) {
            const uint32_t so = lso + it * 32 * 128;       // row += 32 (swizzle uses row&7 only)
            const size_t goA = (size_t)(bm) * DK + lgo + (size_t)it * 32 * DK + k0;
            const size_t goB = (size_t)(bn) * DK + lgo + (size_t)it * 32 * DK + k0;
            cp_async16(st + 0 * BUF_BYTES + so, Xh + goA);
            cp_async16(st + 1 * BUF_BYTES + so, Xl + goA);
            cp_async16(st + 2 * BUF_BYTES + so, Wh + goB);
            cp_async16(st + 3 * BUF_BYTES + so, Wl + goB);
        }
        cp_commit();
    };

    float acc[2][8][4];
#pragma unroll
    for (int i = 0; i < 2; i++)
#pragma unroll
        for (int j = 0; j < 8; j++)
#pragma unroll
            for (int c = 0; c < 4; c++) acc[i][j][c] = 0.0f;

    // ldmatrix per-lane base byte offsets (unswizzled)
    const uint32_t arow = (uint32_t)(wm * 32 + (lane & 15)) * 128 + (uint32_t)(lane >> 4) * 16;
    const uint32_t brow = (uint32_t)(wn * 64 + (lane & 15)) * 128 + (uint32_t)(lane >> 4) * 16;

    load_stage(0, 0);

    for (int s = 0; s < NSTAGES; s++) {
        if (s + 1 < NSTAGES) {
            load_stage(s + 1, (s + 1) & 1);
            cp_wait<1>();
        } else {
            cp_wait<0>();
        }
        __syncthreads();

        const uint32_t st = sbase + (s & 1) * STAGE_BYTES;
        const uint32_t sAh = st + 0 * BUF_BYTES;
        const uint32_t sAl = st + 1 * BUF_BYTES;
        const uint32_t sBh = st + 2 * BUF_BYTES;
        const uint32_t sBl = st + 3 * BUF_BYTES;

#pragma unroll
        for (int kk = 0; kk < 4; kk++) {
            uint32_t ah[2][4], al[2][4], bh[4][4], bl[4][4];
#pragma unroll
            for (int nt = 0; nt < 4; nt++)
                ldsm4(bh[nt], sBh + swz128(brow + nt * 2048 + kk * 32));
#pragma unroll
            for (int mt = 0; mt < 2; mt++)
                ldsm4(ah[mt], sAh + swz128(arow + mt * 2048 + kk * 32));
            // pass 1: Xhi * Whi
#pragma unroll
            for (int mt = 0; mt < 2; mt++)
#pragma unroll
                for (int nt = 0; nt < 4; nt++) {
                    mma16816(acc[mt][nt * 2 + 0], ah[mt], bh[nt][0], bh[nt][2]);
                    mma16816(acc[mt][nt * 2 + 1], ah[mt], bh[nt][1], bh[nt][3]);
                }
            // pass 3: Xlo * Whi (reuse bh)
#pragma unroll
            for (int mt = 0; mt < 2; mt++)
                ldsm4(al[mt], sAl + swz128(arow + mt * 2048 + kk * 32));
#pragma unroll
            for (int mt = 0; mt < 2; mt++)
#pragma unroll
                for (int nt = 0; nt < 4; nt++) {
                    mma16816(acc[mt][nt * 2 + 0], al[mt], bh[nt][0], bh[nt][2]);
                    mma16816(acc[mt][nt * 2 + 1], al[mt], bh[nt][1], bh[nt][3]);
                }
            // pass 2: Xhi * Wlo (reuse ah)
#pragma unroll
            for (int nt = 0; nt < 4; nt++)
                ldsm4(bl[nt], sBl + swz128(brow + nt * 2048 + kk * 32));
#pragma unroll
            for (int mt = 0; mt < 2; mt++)
#pragma unroll
                for (int nt = 0; nt < 4; nt++) {
                    mma16816(acc[mt][nt * 2 + 0], ah[mt], bl[nt][0], bl[nt][2]);
                    mma16816(acc[mt][nt * 2 + 1], ah[mt], bl[nt][1], bl[nt][3]);
                }
        }
        __syncthreads();
    }

    // ---- epilogue: direct stores (float2), + bias ----
    const int qr = lane >> 2;           // 0..7
    const int qc = (lane & 3) * 2;      // 0,2,4,6
#pragma unroll
    for (int mt = 0; mt < 2; mt++) {
        const int r0 = bm + wm * 32 + mt * 16 + qr;
#pragma unroll
        for (int j = 0; j < 8; j++) {
            const int col = bn + wn * 64 + j * 8 + qc;
            const float2 bv = *(const float2*)(bias + col);
            float2 o0, o1;
            o0.x = acc[mt][j][0] + bv.x;
            o0.y = acc[mt][j][1] + bv.y;
            o1.x = acc[mt][j][2] + bv.x;
            o1.y = acc[mt][j][3] + bv.y;
            *(float2*)(C + (size_t)r0 * DN + col) = o0;
            *(float2*)(C + (size_t)(r0 + 8) * DN + col) = o1;
        }
    }
}

// ---------------------------------------------------------------------------
extern "C" void kernel_launch(void* const* d_in, const int* in_sizes, int n_in,
                              void* d_out, int out_size) {
    const float* x    = (const float*)d_in[0];
    const float* w    = (const float*)d_in[1];
    const float* bias = (const float*)d_in[2];
    float* out = (float*)d_out;

    const int M = out_size / DN;                 // 8192

    cudaFuncSetAttribute(gemm_kernel, cudaFuncAttributeMaxDynamicSharedMemorySize, SM_TOTAL);

    const int n_groups = (DN * DK) / GROUP;
    quant_kernel<<<n_groups / 8, 256>>>(w);

    xsplit_kernel<<<((size_t)M * DK) / 4096, 1024>>>(x);

    dim3 grid(DN / BN, M / BM);
    gemm_kernel<<<grid, 256, SM_TOTAL>>>(bias, out);
}

// round 6
// speedup vs baseline: 3.1863x; 1.1679x over previous
#include <cuda_runtime.h>
#include <cuda_bf16.h>
#include <cstdint>

#define DK 4096
#define DN 4096
#define DM 8192
#define GROUP 128
#define NGK (DK / GROUP)       // 32 groups along K
#define EPSQ 1e-8f

#define BM 128
#define BN 128
#define BKE 64                 // K elements per stage (64 bf16 = 128B rows)
#define NSTAGES (DK / BKE)

// ---------------- device scratch (allocation-free rule) ----------------
__device__ __nv_bfloat16 g_q  [(size_t)DN * DK];      // INT2 codes as bf16 (exact)
__device__ float         g_scale[(size_t)NGK * DN];   // [gk][n]
__device__ float         g_mn   [(size_t)NGK * DN];   // [gk][n]
__device__ __nv_bfloat16 g_xhi[(size_t)DM * DK];
__device__ __nv_bfloat16 g_xlo[(size_t)DM * DK];
__device__ float         g_xsum[(size_t)NGK * DM];    // [gk][m] group row-sums of x

// ---------------- PTX helpers (baseline sm_80+ ISA only) ----------------
__device__ __forceinline__ uint32_t smem_u32(const void* p) {
    uint32_t a;
    asm("{ .reg .u64 t; cvta.to.shared.u64 t, %1; cvt.u32.u64 %0, t; }" : "=r"(a) : "l"(p));
    return a;
}
__device__ __forceinline__ uint32_t swz128(uint32_t off) {
    return off ^ ((off >> 3) & 0x70);
}
__device__ __forceinline__ void cp_async16(uint32_t saddr, const void* gaddr) {
    asm volatile("cp.async.cg.shared.global [%0], [%1], 16;" :: "r"(saddr), "l"(gaddr) : "memory");
}
__device__ __forceinline__ void cp_commit() {
    asm volatile("cp.async.commit_group;" ::: "memory");
}
template <int N>
__device__ __forceinline__ void cp_wait() {
    asm volatile("cp.async.wait_group %0;" :: "n"(N) : "memory");
}
__device__ __forceinline__ void ldsm4(uint32_t* r, uint32_t addr) {
    asm volatile("ldmatrix.sync.aligned.m8n8.x4.shared.b16 {%0,%1,%2,%3}, [%4];"
                 : "=r"(r[0]), "=r"(r[1]), "=r"(r[2]), "=r"(r[3]) : "r"(addr));
}
__device__ __forceinline__ void mma16816(float* d, const uint32_t* a, uint32_t b0, uint32_t b1) {
    asm volatile(
        "mma.sync.aligned.m16n8k16.row.col.f32.bf16.bf16.f32 "
        "{%0,%1,%2,%3}, {%4,%5,%6,%7}, {%8,%9}, {%0,%1,%2,%3};"
        : "+f"(d[0]), "+f"(d[1]), "+f"(d[2]), "+f"(d[3])
        : "r"(a[0]), "r"(a[1]), "r"(a[2]), "r"(a[3]), "r"(b0), "r"(b1));
}

// ---------------- Kernel 1: fake-quant -> Q codes + per-group scale/mn ----------------
__global__ __launch_bounds__(256) void quant_kernel(const float* __restrict__ w) {
    const int warp = threadIdx.x >> 5;
    const int lane = threadIdx.x & 31;
    const long g = (long)blockIdx.x * 8 + warp;     // group over flattened W
    const float* p = w + g * GROUP;

    float v[4];
    float mn = INFINITY, mx = -INFINITY;
#pragma unroll
    for (int i = 0; i < 4; i++) {
        v[i] = p[lane + 32 * i];
        mn = fminf(mn, v[i]);
        mx = fmaxf(mx, v[i]);
    }
#pragma unroll
    for (int o = 16; o > 0; o >>= 1) {
        mn = fminf(mn, __shfl_xor_sync(0xffffffffu, mn, o));
        mx = fmaxf(mx, __shfl_xor_sync(0xffffffffu, mx, o));
    }
    const float rng = mx - mn;
    const bool pass = rng < EPSQ;
    const float scale = rng * (1.0f / 3.0f);
    const float sscale = pass ? 1.0f : scale;

#pragma unroll
    for (int i = 0; i < 4; i++) {
        float q = rintf((v[i] - mn) / sscale);      // half-even like jnp.round
        q = fminf(fmaxf(q, 0.0f), 3.0f);
        // passthrough fallback: Q = bf16(w), scale=1, mn=0 (prob ~0 for this data)
        g_q[g * GROUP + lane + 32 * i] = __float2bfloat16(pass ? v[i] : q);
    }
    if (lane == 0) {
        const int n  = (int)(g >> 5);
        const int gk = (int)(g & 31);
        g_scale[(size_t)gk * DN + n] = pass ? 1.0f : scale;
        g_mn   [(size_t)gk * DN + n] = pass ? 0.0f : mn;
    }
}

// ---------------- Kernel 2: bf16 hi/lo split of X + group row-sums ----------------
__global__ __launch_bounds__(256) void xsplit_kernel(const float* __restrict__ x) {
    const int warp = threadIdx.x >> 5;
    const int lane = threadIdx.x & 31;
    const long g = (long)blockIdx.x * 8 + warp;     // group over flattened X
    const float* p = x + g * GROUP;

    float s = 0.0f;
#pragma unroll
    for (int i = 0; i < 4; i++) {
        float v = p[lane + 32 * i];
        s += v;
        __nv_bfloat16 hi = __float2bfloat16(v);
        __nv_bfloat16 lo = __float2bfloat16(v - __bfloat162float(hi));
        g_xhi[g * GROUP + lane + 32 * i] = hi;
        g_xlo[g * GROUP + lane + 32 * i] = lo;
    }
#pragma unroll
    for (int o = 16; o > 0; o >>= 1)
        s += __shfl_xor_sync(0xffffffffu, s, o);
    if (lane == 0) {
        const int m  = (int)(g >> 5);
        const int gk = (int)(g & 31);
        g_xsum[(size_t)gk * DM + m] = s;
    }
}

// ---------------- Kernel 3: mma.sync bf16 GEMM with per-group rescale ----------------
// SMEM: 2 stages x 3 buffers (Ahi, Alo, Q), each 128x64 bf16 = 16KB.
#define BUF_BYTES (128 * 128)          // 128 rows x 128B
#define STAGE_BYTES (3 * BUF_BYTES)    // 48KB
#define SM_TOTAL (2 * STAGE_BYTES)     // 96KB

__global__ __launch_bounds__(512) void gemm_kernel(
    const float* __restrict__ bias, float* __restrict__ C) {

    extern __shared__ char sm[];
    const uint32_t sbase = smem_u32(sm);

    const int tid = threadIdx.x;
    const int wid = tid >> 5;
    const int lane = tid & 31;
    const int wm = wid & 3;           // 0..3 -> warp rows [wm*32, +32)
    const int wn = wid >> 2;          // 0..3 -> warp cols [wn*32, +32)
    const int bn = blockIdx.x * BN;
    const int bm = blockIdx.y * BM;

    const __nv_bfloat16* __restrict__ Xh = g_xhi;
    const __nv_bfloat16* __restrict__ Xl = g_xlo;
    const __nv_bfloat16* __restrict__ Qw = g_q;

    // per-thread load mapping: idx = tid + it*512 in [0,1024): row=idx>>3, chunk=idx&7
    const int lrow = tid >> 3;            // advances by 64 per iteration (row&7 invariant)
    const int lchk = tid & 7;
    const uint32_t lso = swz128(lrow * 128 + lchk * 16);
    const size_t lgo = (size_t)lrow * DK + lchk * 8;

    auto load_stage = [&](int s, int buf) {
        const int k0 = s * BKE;
        const uint32_t st = sbase + buf * STAGE_BYTES;
#pragma unroll
        for (int it = 0; it < 2; it++) {
            const uint32_t so = lso + it * 64 * 128;
            const size_t goA = (size_t)bm * DK + lgo + (size_t)it * 64 * DK + k0;
            const size_t goB = (size_t)bn * DK + lgo + (size_t)it * 64 * DK + k0;
            cp_async16(st + 0 * BUF_BYTES + so, Xh + goA);
            cp_async16(st + 1 * BUF_BYTES + so, Xl + goA);
            cp_async16(st + 2 * BUF_BYTES + so, Qw + goB);
        }
        cp_commit();
    };

    float acc[2][4][4];   // final result accumulators
    float P[2][4][4];     // per-group partial (X . Q^T)
#pragma unroll
    for (int i = 0; i < 2; i++)
#pragma unroll
        for (int j = 0; j < 4; j++)
#pragma unroll
            for (int c = 0; c < 4; c++) { acc[i][j][c] = 0.0f; P[i][j][c] = 0.0f; }

    // ldmatrix per-lane base byte offsets (unswizzled)
    const uint32_t arow = (uint32_t)(wm * 32 + (lane & 15)) * 128 + (uint32_t)(lane >> 4) * 16;
    const uint32_t brow = (uint32_t)(wn * 32 + (lane & 15)) * 128 + (uint32_t)(lane >> 4) * 16;

    const int qr = lane >> 2;           // 0..7
    const int qc = (lane & 3) * 2;      // 0,2,4,6

    load_stage(0, 0);

    for (int s = 0; s < NSTAGES; s++) {
        if (s + 1 < NSTAGES) {
            load_stage(s + 1, (s + 1) & 1);
            cp_wait<1>();
        } else {
            cp_wait<0>();
        }
        __syncthreads();

        const uint32_t st = sbase + (s & 1) * STAGE_BYTES;
        const uint32_t sAh = st + 0 * BUF_BYTES;
        const uint32_t sAl = st + 1 * BUF_BYTES;
        const uint32_t sQ  = st + 2 * BUF_BYTES;

#pragma unroll
        for (int kk = 0; kk < 4; kk++) {
            uint32_t ah[2][4], al[2][4], bq[2][4];
#pragma unroll
            for (int nt = 0; nt < 2; nt++)
                ldsm4(bq[nt], sQ + swz128(brow + nt * 2048 + kk * 32));
#pragma unroll
            for (int mt = 0; mt < 2; mt++)
                ldsm4(ah[mt], sAh + swz128(arow + mt * 2048 + kk * 32));
            // pass 1: Xhi * Q
#pragma unroll
            for (int mt = 0; mt < 2; mt++)
#pragma unroll
                for (int nt = 0; nt < 2; nt++) {
                    mma16816(P[mt][nt * 2 + 0], ah[mt], bq[nt][0], bq[nt][2]);
                    mma16816(P[mt][nt * 2 + 1], ah[mt], bq[nt][1], bq[nt][3]);
                }
            // pass 2: Xlo * Q (reuse bq)
#pragma unroll
            for (int mt = 0; mt < 2; mt++)
                ldsm4(al[mt], sAl + swz128(arow + mt * 2048 + kk * 32));
#pragma unroll
            for (int mt = 0; mt < 2; mt++)
#pragma unroll
                for (int nt = 0; nt < 2; nt++) {
                    mma16816(P[mt][nt * 2 + 0], al[mt], bq[nt][0], bq[nt][2]);
                    mma16816(P[mt][nt * 2 + 1], al[mt], bq[nt][1], bq[nt][3]);
                }
        }

        // ---- group boundary: acc += scale * P + mn * S; P = 0 ----
        if (s & 1) {
            const int gk = s >> 1;
            const float* scp = g_scale + (size_t)gk * DN + bn + wn * 32;
            const float* mnp = g_mn    + (size_t)gk * DN + bn + wn * 32;
            const float* Sp  = g_xsum  + (size_t)gk * DM + bm + wm * 32;
            float Sv[4];
            Sv[0] = __ldg(Sp + qr);      Sv[1] = __ldg(Sp + qr + 8);
            Sv[2] = __ldg(Sp + 16 + qr); Sv[3] = __ldg(Sp + 16 + qr + 8);
#pragma unroll
            for (int n8 = 0; n8 < 4; n8++) {
                const float2 sc = __ldg((const float2*)(scp + n8 * 8 + qc));
                const float2 mv = __ldg((const float2*)(mnp + n8 * 8 + qc));
#pragma unroll
                for (int mt = 0; mt < 2; mt++) {
                    float* a = acc[mt][n8];
                    float* p = P[mt][n8];
                    a[0] += sc.x * p[0] + mv.x * Sv[mt * 2 + 0];
                    a[1] += sc.y * p[1] + mv.y * Sv[mt * 2 + 0];
                    a[2] += sc.x * p[2] + mv.x * Sv[mt * 2 + 1];
                    a[3] += sc.y * p[3] + mv.y * Sv[mt * 2 + 1];
                    p[0] = p[1] = p[2] = p[3] = 0.0f;
                }
            }
        }
        __syncthreads();
    }

    // ---- epilogue: + bias, float2 stores ----
#pragma unroll
    for (int mt = 0; mt < 2; mt++) {
        const int r0 = bm + wm * 32 + mt * 16 + qr;
#pragma unroll
        for (int n8 = 0; n8 < 4; n8++) {
            const int col = bn + wn * 32 + n8 * 8 + qc;
            const float2 bv = *(const float2*)(bias + col);
            float2 o0, o1;
            o0.x = acc[mt][n8][0] + bv.x;
            o0.y = acc[mt][n8][1] + bv.y;
            o1.x = acc[mt][n8][2] + bv.x;
            o1.y = acc[mt][n8][3] + bv.y;
            *(float2*)(C + (size_t)r0 * DN + col) = o0;
            *(float2*)(C + (size_t)(r0 + 8) * DN + col) = o1;
        }
    }
}

// ---------------------------------------------------------------------------
extern "C" void kernel_launch(void* const* d_in, const int* in_sizes, int n_in,
                              void* d_out, int out_size) {
    const float* x    = (const float*)d_in[0];
    const float* w    = (const float*)d_in[1];
    const float* bias = (const float*)d_in[2];
    float* out = (float*)d_out;

    cudaFuncSetAttribute(gemm_kernel, cudaFuncAttributeMaxDynamicSharedMemorySize, SM_TOTAL);

    quant_kernel<<<(DN * DK / GROUP) / 8, 256>>>(w);
    xsplit_kernel<<<((size_t)DM * DK / GROUP) / 8, 256>>>(x);

    dim3 grid(DN / BN, DM / BM);
    gemm_kernel<<<grid, 512, SM_TOTAL>>>(bias, out);
}

// round 7
// speedup vs baseline: 7.2472x; 2.2745x over previous
#include <cuda_runtime.h>
#include <cuda_fp16.h>
#include <cuda_bf16.h>
#include <cstdint>

#define DK 4096
#define DN 4096
#define DM 8192
#define GROUP 128
#define EPSQ 1e-8f

#define BM 128
#define BN 256
#define BKE 64                 // K elements per stage (64 fp16 = 128B rows)
#define NSTAGES (DK / BKE)
#define NBUF 4

// ---------------- device scratch (allocation-free rule) ----------------
__device__ __half g_wq [(size_t)DN * DK];   // dequantized weight, fp16
__device__ __half g_xh [(size_t)DM * DK];   // x, fp16

// ---------------- PTX helpers (baseline sm_80+ ISA only) ----------------
__device__ __forceinline__ uint32_t smem_u32(const void* p) {
    uint32_t a;
    asm("{ .reg .u64 t; cvta.to.shared.u64 t, %1; cvt.u32.u64 %0, t; }" : "=r"(a) : "l"(p));
    return a;
}
__device__ __forceinline__ uint32_t swz128(uint32_t off) {
    return off ^ ((off >> 3) & 0x70);
}
__device__ __forceinline__ void cp_async16(uint32_t saddr, const void* gaddr) {
    asm volatile("cp.async.cg.shared.global [%0], [%1], 16;" :: "r"(saddr), "l"(gaddr) : "memory");
}
__device__ __forceinline__ void cp_commit() {
    asm volatile("cp.async.commit_group;" ::: "memory");
}
template <int N>
__device__ __forceinline__ void cp_wait() {
    asm volatile("cp.async.wait_group %0;" :: "n"(N) : "memory");
}
__device__ __forceinline__ void ldsm4(uint32_t* r, uint32_t addr) {
    asm volatile("ldmatrix.sync.aligned.m8n8.x4.shared.b16 {%0,%1,%2,%3}, [%4];"
                 : "=r"(r[0]), "=r"(r[1]), "=r"(r[2]), "=r"(r[3]) : "r"(addr));
}
__device__ __forceinline__ void mma16816(float* d, const uint32_t* a, uint32_t b0, uint32_t b1) {
    asm volatile(
        "mma.sync.aligned.m16n8k16.row.col.f32.f16.f16.f32 "
        "{%0,%1,%2,%3}, {%4,%5,%6,%7}, {%8,%9}, {%0,%1,%2,%3};"
        : "+f"(d[0]), "+f"(d[1]), "+f"(d[2]), "+f"(d[3])
        : "r"(a[0]), "r"(a[1]), "r"(a[2]), "r"(a[3]), "r"(b0), "r"(b1));
}

// ---------------- Kernel 1: fake-quant -> dequantized fp16 W ----------------
__global__ __launch_bounds__(256) void quant_kernel(const float* __restrict__ w) {
    const int warp = threadIdx.x >> 5;
    const int lane = threadIdx.x & 31;
    const long g = (long)blockIdx.x * 8 + warp;     // group over flattened W
    const float* p = w + g * GROUP;

    float v[4];
    float mn = INFINITY, mx = -INFINITY;
#pragma unroll
    for (int i = 0; i < 4; i++) {
        v[i] = p[lane + 32 * i];
        mn = fminf(mn, v[i]);
        mx = fmaxf(mx, v[i]);
    }
#pragma unroll
    for (int o = 16; o > 0; o >>= 1) {
        mn = fminf(mn, __shfl_xor_sync(0xffffffffu, mn, o));
        mx = fmaxf(mx, __shfl_xor_sync(0xffffffffu, mx, o));
    }
    const float rng = mx - mn;
    const bool pass = rng < EPSQ;
    const float scale = rng * (1.0f / 3.0f);
    const float sscale = pass ? 1.0f : scale;

#pragma unroll
    for (int i = 0; i < 4; i++) {
        float q = rintf((v[i] - mn) / sscale);      // half-even like jnp.round
        q = fminf(fmaxf(q, 0.0f), 3.0f);
        float deq = pass ? v[i] : (q * scale + mn);
        g_wq[g * GROUP + lane + 32 * i] = __float2half(deq);
    }
}

// ---------------- Kernel 2: X -> fp16 ----------------
__global__ __launch_bounds__(1024) void xhalf_kernel(const float* __restrict__ x) {
    const size_t i4 = (size_t)blockIdx.x * 1024 + threadIdx.x;
    float4 v = ((const float4*)x)[i4];
    __half h[4];
    h[0] = __float2half(v.x);
    h[1] = __float2half(v.y);
    h[2] = __float2half(v.z);
    h[3] = __float2half(v.w);
    *(uint2*)&g_xh[i4 * 4] = *(uint2*)h;
}

// ---------------- Kernel 3: single-pass fp16 mma.sync GEMM ----------------
// SMEM per stage: A 128x64 fp16 (16KB) + B 256x64 fp16 (32KB) = 48KB; 4 stages.
#define A_BYTES (128 * 128)
#define B_BYTES (256 * 128)
#define STAGE_BYTES (A_BYTES + B_BYTES)        // 48KB
#define SM_TOTAL (NBUF * STAGE_BYTES)          // 192KB

__global__ __launch_bounds__(256, 1) void gemm_kernel(
    const float* __restrict__ bias, float* __restrict__ C) {

    extern __shared__ char sm[];
    const uint32_t sbase = smem_u32(sm);

    const int tid = threadIdx.x;
    const int wid = tid >> 5;
    const int lane = tid & 31;
    const int wm = wid & 1;           // 0..1 -> warp rows [wm*64, +64)
    const int wn = wid >> 1;          // 0..3 -> warp cols [wn*64, +64)
    const int bn = blockIdx.x * BN;
    const int bm = blockIdx.y * BM;

    const __half* __restrict__ X = g_xh;
    const __half* __restrict__ W = g_wq;

    // loader mapping: 16B chunks; A: 1024 chunks (4/thread), B: 2048 (8/thread)
    const int lrow = tid >> 3;            // 0..31, advances by 32
    const int lchk = tid & 7;
    const uint32_t lso = swz128(lrow * 128 + lchk * 16);   // swizzle invariant to row+=32
    const size_t lgo = (size_t)lrow * DK + lchk * 8;

    auto load_stage = [&](int s, int buf) {
        const int k0 = s * BKE;
        const uint32_t st = sbase + buf * STAGE_BYTES;
#pragma unroll
        for (int it = 0; it < 4; it++) {
            cp_async16(st + lso + it * 32 * 128,
                       X + (size_t)bm * DK + lgo + (size_t)it * 32 * DK + k0);
        }
#pragma unroll
        for (int it = 0; it < 8; it++) {
            cp_async16(st + A_BYTES + lso + it * 32 * 128,
                       W + (size_t)bn * DK + lgo + (size_t)it * 32 * DK + k0);
        }
        cp_commit();
    };

    float acc[4][4][4];   // [mt][nt][{n8lo: c0 c1, n8hi uses c2..}] -> see mma packing
    // layout: acc[mt][nt] covers m16 x n16 as two n8 MMAs -> need [4][8][4]; flatten:
    float accb[4][8][4];
#pragma unroll
    for (int i = 0; i < 4; i++)
#pragma unroll
        for (int j = 0; j < 8; j++)
#pragma unroll
            for (int c = 0; c < 4; c++) accb[i][j][c] = 0.0f;
    (void)acc;

    // ldmatrix per-lane base byte offsets (unswizzled)
    const uint32_t arow = (uint32_t)(wm * 64 + (lane & 15)) * 128 + (uint32_t)(lane >> 4) * 16;
    const uint32_t brow = (uint32_t)(wn * 64 + (lane & 15)) * 128 + (uint32_t)(lane >> 4) * 16;

    // preload 3 stages
    load_stage(0, 0);
    load_stage(1, 1);
    load_stage(2, 2);

    for (int s = 0; s < NSTAGES; s++) {
        cp_wait<2>();
        __syncthreads();
        if (s + 3 < NSTAGES) load_stage(s + 3, (s + 3) & (NBUF - 1));

        const uint32_t st = sbase + (s & (NBUF - 1)) * STAGE_BYTES;
        const uint32_t sA = st;
        const uint32_t sB = st + A_BYTES;

#pragma unroll
        for (int kk = 0; kk < 4; kk++) {
            uint32_t a[4][4], b[4][4];
#pragma unroll
            for (int nt = 0; nt < 4; nt++)
                ldsm4(b[nt], sB + swz128(brow + nt * 2048 + kk * 32));
#pragma unroll
            for (int mt = 0; mt < 4; mt++)
                ldsm4(a[mt], sA + swz128(arow + mt * 2048 + kk * 32));
#pragma unroll
            for (int mt = 0; mt < 4; mt++)
#pragma unroll
                for (int nt = 0; nt < 4; nt++) {
                    mma16816(accb[mt][nt * 2 + 0], a[mt], b[nt][0], b[nt][2]);
                    mma16816(accb[mt][nt * 2 + 1], a[mt], b[nt][1], b[nt][3]);
                }
        }
        // no trailing sync needed: next iteration's cp_wait + syncthreads gates
        // buffer reuse (stage s+4's load is only issued after that barrier).
    }

    // ---- epilogue: + bias, float2 stores ----
    const int qr = lane >> 2;           // 0..7
    const int qc = (lane & 3) * 2;      // 0,2,4,6
#pragma unroll
    for (int mt = 0; mt < 4; mt++) {
        const int r0 = bm + wm * 64 + mt * 16 + qr;
#pragma unroll
        for (int n8 = 0; n8 < 8; n8++) {
            const int col = bn + wn * 64 + n8 * 8 + qc;
            const float2 bv = *(const float2*)(bias + col);
            float2 o0, o1;
            o0.x = accb[mt][n8][0] + bv.x;
            o0.y = accb[mt][n8][1] + bv.y;
            o1.x = accb[mt][n8][2] + bv.x;
            o1.y = accb[mt][n8][3] + bv.y;
            *(float2*)(C + (size_t)r0 * DN + col) = o0;
            *(float2*)(C + (size_t)(r0 + 8) * DN + col) = o1;
        }
    }
}

// ---------------------------------------------------------------------------
extern "C" void kernel_launch(void* const* d_in, const int* in_sizes, int n_in,
                              void* d_out, int out_size) {
    const float* x    = (const float*)d_in[0];
    const float* w    = (const float*)d_in[1];
    const float* bias = (const float*)d_in[2];
    float* out = (float*)d_out;

    cudaFuncSetAttribute(gemm_kernel, cudaFuncAttributeMaxDynamicSharedMemorySize, SM_TOTAL);

    quant_kernel<<<(DN * DK / GROUP) / 8, 256>>>(w);
    xhalf_kernel<<<((size_t)DM * DK) / 4096, 1024>>>(x);

    dim3 grid(DN / BN, DM / BM);
    gemm_kernel<<<grid, 256, SM_TOTAL>>>(bias, out);
}

// round 8
// speedup vs baseline: 7.3325x; 1.0118x over previous
#include <cuda_runtime.h>
#include <cuda_fp16.h>
#include <cstdint>

#define DK 4096
#define DN 4096
#define DM 8192
#define GROUP 128
#define EPSQ 1e-8f

#define BM 128
#define BN 256
#define BKE 64                 // K elements per stage (64 fp16 = 128B rows)
#define NSTAGES (DK / BKE)
#define NBUF 4

// ---------------- device scratch (allocation-free rule) ----------------
__device__ __half g_wq [(size_t)DN * DK];   // dequantized weight, fp16
__device__ __half g_xh [(size_t)DM * DK];   // x, fp16

// ---------------- PTX helpers (baseline sm_80+ ISA only) ----------------
__device__ __forceinline__ uint32_t smem_u32(const void* p) {
    uint32_t a;
    asm("{ .reg .u64 t; cvta.to.shared.u64 t, %1; cvt.u32.u64 %0, t; }" : "=r"(a) : "l"(p));
    return a;
}
__device__ __forceinline__ uint32_t swz128(uint32_t off) {
    return off ^ ((off >> 3) & 0x70);
}
__device__ __forceinline__ void cp_async16(uint32_t saddr, const void* gaddr) {
    asm volatile("cp.async.cg.shared.global [%0], [%1], 16;" :: "r"(saddr), "l"(gaddr) : "memory");
}
__device__ __forceinline__ void cp_commit() {
    asm volatile("cp.async.commit_group;" ::: "memory");
}
template <int N>
__device__ __forceinline__ void cp_wait() {
    asm volatile("cp.async.wait_group %0;" :: "n"(N) : "memory");
}
__device__ __forceinline__ void ldsm4(uint32_t* r, uint32_t addr) {
    asm volatile("ldmatrix.sync.aligned.m8n8.x4.shared.b16 {%0,%1,%2,%3}, [%4];"
                 : "=r"(r[0]), "=r"(r[1]), "=r"(r[2]), "=r"(r[3]) : "r"(addr));
}
__device__ __forceinline__ void mma16816(float* d, const uint32_t* a, uint32_t b0, uint32_t b1) {
    asm volatile(
        "mma.sync.aligned.m16n8k16.row.col.f32.f16.f16.f32 "
        "{%0,%1,%2,%3}, {%4,%5,%6,%7}, {%8,%9}, {%0,%1,%2,%3};"
        : "+f"(d[0]), "+f"(d[1]), "+f"(d[2]), "+f"(d[3])
        : "r"(a[0]), "r"(a[1]), "r"(a[2]), "r"(a[3]), "r"(b0), "r"(b1));
}

// ---------------- Kernel 1: fake-quant -> dequantized fp16 W ----------------
// One warp per group; each thread holds 4 consecutive floats (float4 load).
__global__ __launch_bounds__(256) void quant_kernel(const float* __restrict__ w) {
    const int warp = threadIdx.x >> 5;
    const int lane = threadIdx.x & 31;
    const long g = (long)blockIdx.x * 8 + warp;     // group over flattened W

    const float4 v4 = ((const float4*)(w + g * GROUP))[lane];
    float v[4] = {v4.x, v4.y, v4.z, v4.w};

    float mn = fminf(fminf(v[0], v[1]), fminf(v[2], v[3]));
    float mx = fmaxf(fmaxf(v[0], v[1]), fmaxf(v[2], v[3]));
#pragma unroll
    for (int o = 16; o > 0; o >>= 1) {
        mn = fminf(mn, __shfl_xor_sync(0xffffffffu, mn, o));
        mx = fmaxf(mx, __shfl_xor_sync(0xffffffffu, mx, o));
    }
    const float rng = mx - mn;
    const bool pass = rng < EPSQ;
    const float scale = rng * (1.0f / 3.0f);
    const float inv = pass ? 1.0f : (1.0f / scale);

    __half h[4];
#pragma unroll
    for (int i = 0; i < 4; i++) {
        float q = rintf((v[i] - mn) * inv);         // half-even like jnp.round
        q = fminf(fmaxf(q, 0.0f), 3.0f);
        float deq = pass ? v[i] : fmaf(q, scale, mn);
        h[i] = __float2half(deq);
    }
    ((uint2*)(g_wq + g * GROUP))[lane] = *(uint2*)h;
}

// ---------------- Kernel 2: X -> fp16 ----------------
__global__ __launch_bounds__(1024) void xhalf_kernel(const float* __restrict__ x) {
    const size_t i4 = (size_t)blockIdx.x * 1024 + threadIdx.x;
    float4 v = ((const float4*)x)[i4];
    __half h[4];
    h[0] = __float2half(v.x);
    h[1] = __float2half(v.y);
    h[2] = __float2half(v.z);
    h[3] = __float2half(v.w);
    *(uint2*)&g_xh[i4 * 4] = *(uint2*)h;
}

// ---------------- Kernel 3: single-pass fp16 mma.sync GEMM ----------------
// SMEM per stage: A 128x64 fp16 (16KB) + B 256x64 fp16 (32KB) = 48KB; 4 stages.
#define A_BYTES (128 * 128)
#define B_BYTES (256 * 128)
#define STAGE_BYTES (A_BYTES + B_BYTES)        // 48KB
#define SM_TOTAL (NBUF * STAGE_BYTES)          // 192KB

__global__ __launch_bounds__(256, 1) void gemm_kernel(
    const float* __restrict__ bias, float* __restrict__ C) {

    extern __shared__ char sm[];
    const uint32_t sbase = smem_u32(sm);

    const int tid = threadIdx.x;
    const int wid = tid >> 5;
    const int lane = tid & 31;
    const int wm = wid & 1;           // 0..1 -> warp rows [wm*64, +64)
    const int wn = wid >> 1;          // 0..3 -> warp cols [wn*64, +64)
    const int bn = blockIdx.x * BN;
    const int bm = blockIdx.y * BM;

    const __half* __restrict__ X = g_xh;
    const __half* __restrict__ W = g_wq;

    // loader mapping: 16B chunks; A: 1024 chunks (4/thread), B: 2048 (8/thread)
    const int lrow = tid >> 3;            // 0..31, advances by 32
    const int lchk = tid & 7;
    const uint32_t lso = swz128(lrow * 128 + lchk * 16);   // swizzle invariant to row+=32
    const size_t lgo = (size_t)lrow * DK + lchk * 8;

    auto load_stage = [&](int s, int buf) {
        const int k0 = s * BKE;
        const uint32_t st = sbase + buf * STAGE_BYTES;
#pragma unroll
        for (int it = 0; it < 4; it++) {
            cp_async16(st + lso + it * 32 * 128,
                       X + (size_t)bm * DK + lgo + (size_t)it * 32 * DK + k0);
        }
#pragma unroll
        for (int it = 0; it < 8; it++) {
            cp_async16(st + A_BYTES + lso + it * 32 * 128,
                       W + (size_t)bn * DK + lgo + (size_t)it * 32 * DK + k0);
        }
        cp_commit();
    };

    float accb[4][8][4];
#pragma unroll
    for (int i = 0; i < 4; i++)
#pragma unroll
        for (int j = 0; j < 8; j++)
#pragma unroll
            for (int c = 0; c < 4; c++) accb[i][j][c] = 0.0f;

    // ldmatrix per-lane base byte offsets (unswizzled)
    const uint32_t arow = (uint32_t)(wm * 64 + (lane & 15)) * 128 + (uint32_t)(lane >> 4) * 16;
    const uint32_t brow = (uint32_t)(wn * 64 + (lane & 15)) * 128 + (uint32_t)(lane >> 4) * 16;

    // preload 3 stages
    load_stage(0, 0);
    load_stage(1, 1);
    load_stage(2, 2);

    for (int s = 0; s < NSTAGES; s++) {
        cp_wait<2>();
        __syncthreads();
        if (s + 3 < NSTAGES) load_stage(s + 3, (s + 3) & (NBUF - 1));

        const uint32_t st = sbase + (s & (NBUF - 1)) * STAGE_BYTES;
        const uint32_t sA = st;
        const uint32_t sB = st + A_BYTES;

        // ---- fragment ping-pong: prefetch kk+1 while issuing kk's MMAs ----
        uint32_t a[2][4][4], b[2][4][4];
#pragma unroll
        for (int nt = 0; nt < 4; nt++)
            ldsm4(b[0][nt], sB + swz128(brow + nt * 2048));
#pragma unroll
        for (int mt = 0; mt < 4; mt++)
            ldsm4(a[0][mt], sA + swz128(arow + mt * 2048));

#pragma unroll
        for (int kk = 0; kk < 4; kk++) {
            const int cur = kk & 1;
            const int nxt = cur ^ 1;
            if (kk < 3) {
#pragma unroll
                for (int nt = 0; nt < 4; nt++)
                    ldsm4(b[nxt][nt], sB + swz128(brow + nt * 2048 + (kk + 1) * 32));
#pragma unroll
                for (int mt = 0; mt < 4; mt++)
                    ldsm4(a[nxt][mt], sA + swz128(arow + mt * 2048 + (kk + 1) * 32));
            }
#pragma unroll
            for (int mt = 0; mt < 4; mt++)
#pragma unroll
                for (int nt = 0; nt < 4; nt++) {
                    mma16816(accb[mt][nt * 2 + 0], a[cur][mt], b[cur][nt][0], b[cur][nt][2]);
                    mma16816(accb[mt][nt * 2 + 1], a[cur][mt], b[cur][nt][1], b[cur][nt][3]);
                }
        }
        // buffer reuse gated by next iteration's cp_wait + syncthreads
    }

    // ---- epilogue: + bias, float2 stores ----
    const int qr = lane >> 2;           // 0..7
    const int qc = (lane & 3) * 2;      // 0,2,4,6
#pragma unroll
    for (int mt = 0; mt < 4; mt++) {
        const int r0 = bm + wm * 64 + mt * 16 + qr;
#pragma unroll
        for (int n8 = 0; n8 < 8; n8++) {
            const int col = bn + wn * 64 + n8 * 8 + qc;
            const float2 bv = *(const float2*)(bias + col);
            float2 o0, o1;
            o0.x = accb[mt][n8][0] + bv.x;
            o0.y = accb[mt][n8][1] + bv.y;
            o1.x = accb[mt][n8][2] + bv.x;
            o1.y = accb[mt][n8][3] + bv.y;
            *(float2*)(C + (size_t)r0 * DN + col) = o0;
            *(float2*)(C + (size_t)(r0 + 8) * DN + col) = o1;
        }
    }
}

// ---------------------------------------------------------------------------
extern "C" void kernel_launch(void* const* d_in, const int* in_sizes, int n_in,
                              void* d_out, int out_size) {
    const float* x    = (const float*)d_in[0];
    const float* w    = (const float*)d_in[1];
    const float* bias = (const float*)d_in[2];
    float* out = (float*)d_out;

    cudaFuncSetAttribute(gemm_kernel, cudaFuncAttributeMaxDynamicSharedMemorySize, SM_TOTAL);

    quant_kernel<<<(DN * DK / GROUP) / 8, 256>>>(w);
    xhalf_kernel<<<((size_t)DM * DK) / 4096, 1024>>>(x);

    dim3 grid(DN / BN, DM / BM);
    gemm_kernel<<<grid, 256, SM_TOTAL>>>(bias, out);
}

// round 9
// speedup vs baseline: 7.4278x; 1.0130x over previous
#include <cuda_runtime.h>
#include <cuda_fp16.h>
#include <cstdint>

#define DK 4096
#define DN 4096
#define DM 8192
#define GROUP 128
#define EPSQ 1e-8f

#define BM 128
#define BN 256
#define BKE 64                 // K elements per stage (64 fp16 = 128B rows)
#define NSTAGES (DK / BKE)
#define NBUF 4

// ---------------- device scratch (allocation-free rule) ----------------
__device__ __half g_wq [(size_t)DN * DK];   // dequantized weight, fp16
__device__ __half g_xh [(size_t)DM * DK];   // x, fp16

// ---------------- PTX helpers (baseline sm_80+ ISA only) ----------------
__device__ __forceinline__ uint32_t smem_u32(const void* p) {
    uint32_t a;
    asm("{ .reg .u64 t; cvta.to.shared.u64 t, %1; cvt.u32.u64 %0, t; }" : "=r"(a) : "l"(p));
    return a;
}
__device__ __forceinline__ uint32_t swz128(uint32_t off) {
    return off ^ ((off >> 3) & 0x70);
}
__device__ __forceinline__ void cp_async16(uint32_t saddr, const void* gaddr) {
    asm volatile("cp.async.cg.shared.global [%0], [%1], 16;" :: "r"(saddr), "l"(gaddr) : "memory");
}
__device__ __forceinline__ void cp_commit() {
    asm volatile("cp.async.commit_group;" ::: "memory");
}
template <int N>
__device__ __forceinline__ void cp_wait() {
    asm volatile("cp.async.wait_group %0;" :: "n"(N) : "memory");
}
__device__ __forceinline__ void ldsm4(uint32_t* r, uint32_t addr) {
    asm volatile("ldmatrix.sync.aligned.m8n8.x4.shared.b16 {%0,%1,%2,%3}, [%4];"
                 : "=r"(r[0]), "=r"(r[1]), "=r"(r[2]), "=r"(r[3]) : "r"(addr));
}
__device__ __forceinline__ void mma16816(float* d, const uint32_t* a, uint32_t b0, uint32_t b1) {
    asm volatile(
        "mma.sync.aligned.m16n8k16.row.col.f32.f16.f16.f32 "
        "{%0,%1,%2,%3}, {%4,%5,%6,%7}, {%8,%9}, {%0,%1,%2,%3};"
        : "+f"(d[0]), "+f"(d[1]), "+f"(d[2]), "+f"(d[3])
        : "r"(a[0]), "r"(a[1]), "r"(a[2]), "r"(a[3]), "r"(b0), "r"(b1));
}

// ---------------- Kernel 1 (fused prep): W fake-quant->fp16  +  X->fp16 ----------------
// Blocks [0, WBLOCKS): weight quant, 8 groups per block (1 warp each).
// Blocks [WBLOCKS, WBLOCKS+XBLOCKS): X fp32->fp16, 8 float4 per thread.
#define WBLOCKS ((DN * DK / GROUP) / 8)              // 16384
#define XBLOCKS 4096
#define XSTRIDE (XBLOCKS * 256)                      // float4 stride per iteration

__global__ __launch_bounds__(256) void prep_kernel(const float* __restrict__ w,
                                                   const float* __restrict__ x) {
    const int bx = blockIdx.x;
    if (bx < WBLOCKS) {
        // ---- weight fake-quant ----
        const int warp = threadIdx.x >> 5;
        const int lane = threadIdx.x & 31;
        const long g = (long)bx * 8 + warp;          // group over flattened W

        const float4 v4 = ((const float4*)(w + g * GROUP))[lane];
        float v[4] = {v4.x, v4.y, v4.z, v4.w};

        float mn = fminf(fminf(v[0], v[1]), fminf(v[2], v[3]));
        float mx = fmaxf(fmaxf(v[0], v[1]), fmaxf(v[2], v[3]));
#pragma unroll
        for (int o = 16; o > 0; o >>= 1) {
            mn = fminf(mn, __shfl_xor_sync(0xffffffffu, mn, o));
            mx = fmaxf(mx, __shfl_xor_sync(0xffffffffu, mx, o));
        }
        const float rng = mx - mn;
        const bool pass = rng < EPSQ;
        const float scale = rng * (1.0f / 3.0f);
        const float inv = pass ? 1.0f : (1.0f / scale);

        __half h[4];
#pragma unroll
        for (int i = 0; i < 4; i++) {
            float q = rintf((v[i] - mn) * inv);      // half-even like jnp.round
            q = fminf(fmaxf(q, 0.0f), 3.0f);
            float deq = pass ? v[i] : fmaf(q, scale, mn);
            h[i] = __float2half(deq);
        }
        ((uint2*)(g_wq + g * GROUP))[lane] = *(uint2*)h;
    } else {
        // ---- X convert ----
        const size_t base = (size_t)(bx - WBLOCKS) * 256 + threadIdx.x;
        const float4* __restrict__ xp = (const float4*)x;
#pragma unroll
        for (int i = 0; i < 8; i++) {
            const size_t i4 = base + (size_t)i * XSTRIDE;
            float4 v = xp[i4];
            __half h[4];
            h[0] = __float2half(v.x);
            h[1] = __float2half(v.y);
            h[2] = __float2half(v.z);
            h[3] = __float2half(v.w);
            *(uint2*)&g_xh[i4 * 4] = *(uint2*)h;
        }
    }
}

// ---------------- Kernel 2: single-pass fp16 mma.sync GEMM ----------------
// SMEM per stage: A 128x64 fp16 (16KB) + B 256x64 fp16 (32KB) = 48KB; 4 stages.
#define A_BYTES (128 * 128)
#define B_BYTES (256 * 128)
#define STAGE_BYTES (A_BYTES + B_BYTES)        // 48KB
#define SM_TOTAL (NBUF * STAGE_BYTES)          // 192KB

__global__ __launch_bounds__(256, 1) void gemm_kernel(
    const float* __restrict__ bias, float* __restrict__ C) {

    extern __shared__ char sm[];
    const uint32_t sbase = smem_u32(sm);

    const int tid = threadIdx.x;
    const int wid = tid >> 5;
    const int lane = tid & 31;
    const int wm = wid & 1;           // 0..1 -> warp rows [wm*64, +64)
    const int wn = wid >> 1;          // 0..3 -> warp cols [wn*64, +64)
    const int bn = blockIdx.x * BN;
    const int bm = blockIdx.y * BM;

    const __half* __restrict__ X = g_xh;
    const __half* __restrict__ W = g_wq;

    // loader mapping: 16B chunks; A: 1024 chunks (4/thread), B: 2048 (8/thread)
    const int lrow = tid >> 3;            // 0..31, advances by 32
    const int lchk = tid & 7;
    const uint32_t lso = swz128(lrow * 128 + lchk * 16);   // swizzle invariant to row+=32
    const size_t lgo = (size_t)lrow * DK + lchk * 8;

    auto load_stage = [&](int s, int buf) {
        const int k0 = s * BKE;
        const uint32_t st = sbase + buf * STAGE_BYTES;
#pragma unroll
        for (int it = 0; it < 4; it++) {
            cp_async16(st + lso + it * 32 * 128,
                       X + (size_t)bm * DK + lgo + (size_t)it * 32 * DK + k0);
        }
#pragma unroll
        for (int it = 0; it < 8; it++) {
            cp_async16(st + A_BYTES + lso + it * 32 * 128,
                       W + (size_t)bn * DK + lgo + (size_t)it * 32 * DK + k0);
        }
        cp_commit();
    };

    float accb[4][8][4];
#pragma unroll
    for (int i = 0; i < 4; i++)
#pragma unroll
        for (int j = 0; j < 8; j++)
#pragma unroll
            for (int c = 0; c < 4; c++) accb[i][j][c] = 0.0f;

    // ldmatrix per-lane base byte offsets (unswizzled)
    const uint32_t arow = (uint32_t)(wm * 64 + (lane & 15)) * 128 + (uint32_t)(lane >> 4) * 16;
    const uint32_t brow = (uint32_t)(wn * 64 + (lane & 15)) * 128 + (uint32_t)(lane >> 4) * 16;

    // preload 3 stages
    load_stage(0, 0);
    load_stage(1, 1);
    load_stage(2, 2);

    for (int s = 0; s < NSTAGES; s++) {
        cp_wait<2>();
        __syncthreads();
        if (s + 3 < NSTAGES) load_stage(s + 3, (s + 3) & (NBUF - 1));

        const uint32_t st = sbase + (s & (NBUF - 1)) * STAGE_BYTES;
        const uint32_t sA = st;
        const uint32_t sB = st + A_BYTES;

        // ---- fragment ping-pong: prefetch kk+1 while issuing kk's MMAs ----
        uint32_t a[2][4][4], b[2][4][4];
#pragma unroll
        for (int nt = 0; nt < 4; nt++)
            ldsm4(b[0][nt], sB + swz128(brow + nt * 2048));
#pragma unroll
        for (int mt = 0; mt < 4; mt++)
            ldsm4(a[0][mt], sA + swz128(arow + mt * 2048));

#pragma unroll
        for (int kk = 0; kk < 4; kk++) {
            const int cur = kk & 1;
            const int nxt = cur ^ 1;
            if (kk < 3) {
#pragma unroll
                for (int nt = 0; nt < 4; nt++)
                    ldsm4(b[nxt][nt], sB + swz128(brow + nt * 2048 + (kk + 1) * 32));
#pragma unroll
                for (int mt = 0; mt < 4; mt++)
                    ldsm4(a[nxt][mt], sA + swz128(arow + mt * 2048 + (kk + 1) * 32));
            }
#pragma unroll
            for (int mt = 0; mt < 4; mt++)
#pragma unroll
                for (int nt = 0; nt < 4; nt++) {
                    mma16816(accb[mt][nt * 2 + 0], a[cur][mt], b[cur][nt][0], b[cur][nt][2]);
                    mma16816(accb[mt][nt * 2 + 1], a[cur][mt], b[cur][nt][1], b[cur][nt][3]);
                }
        }
        // buffer reuse gated by next iteration's cp_wait + syncthreads
    }

    // ---- epilogue: + bias, float2 stores ----
    const int qr = lane >> 2;           // 0..7
    const int qc = (lane & 3) * 2;      // 0,2,4,6
#pragma unroll
    for (int mt = 0; mt < 4; mt++) {
        const int r0 = bm + wm * 64 + mt * 16 + qr;
#pragma unroll
        for (int n8 = 0; n8 < 8; n8++) {
            const int col = bn + wn * 64 + n8 * 8 + qc;
            const float2 bv = *(const float2*)(bias + col);
            float2 o0, o1;
            o0.x = accb[mt][n8][0] + bv.x;
            o0.y = accb[mt][n8][1] + bv.y;
            o1.x = accb[mt][n8][2] + bv.x;
            o1.y = accb[mt][n8][3] + bv.y;
            *(float2*)(C + (size_t)r0 * DN + col) = o0;
            *(float2*)(C + (size_t)(r0 + 8) * DN + col) = o1;
        }
    }
}

// ---------------------------------------------------------------------------
extern "C" void kernel_launch(void* const* d_in, const int* in_sizes, int n_in,
                              void* d_out, int out_size) {
    const float* x    = (const float*)d_in[0];
    const float* w    = (const float*)d_in[1];
    const float* bias = (const float*)d_in[2];
    float* out = (float*)d_out;

    cudaFuncSetAttribute(gemm_kernel, cudaFuncAttributeMaxDynamicSharedMemorySize, SM_TOTAL);

    prep_kernel<<<WBLOCKS + XBLOCKS, 256>>>(w, x);

    dim3 grid(DN / BN, DM / BM);
    gemm_kernel<<<grid, 256, SM_TOTAL>>>(bias, out);
}

// round 11
// speedup vs baseline: 7.6471x; 1.0295x over previous
#include <cuda_runtime.h>
#include <cuda_fp16.h>
#include <cstdint>

#define DK 4096
#define DN 4096
#define DM 8192
#define GROUP 128
#define EPSQ 1e-8f

#define BM 128
#define BN 256
#define BKE 64                 // K elements per stage (64 fp16 = 128B rows)
#define NSTAGES (DK / BKE)
#define NBUF 4

// ---------------- device scratch (allocation-free rule) ----------------
__device__ __half g_wq [(size_t)DN * DK];   // dequantized weight, fp16
__device__ __half g_xh [(size_t)DM * DK];   // x, fp16

// ---------------- PTX helpers (baseline sm_80+ ISA only) ----------------
__device__ __forceinline__ uint32_t smem_u32(const void* p) {
    uint32_t a;
    asm("{ .reg .u64 t; cvta.to.shared.u64 t, %1; cvt.u32.u64 %0, t; }" : "=r"(a) : "l"(p));
    return a;
}
__device__ __forceinline__ uint32_t swz128(uint32_t off) {
    return off ^ ((off >> 3) & 0x70);
}
__device__ __forceinline__ void cp_async16(uint32_t saddr, const void* gaddr) {
    asm volatile("cp.async.cg.shared.global [%0], [%1], 16;" :: "r"(saddr), "l"(gaddr) : "memory");
}
__device__ __forceinline__ void cp_commit() {
    asm volatile("cp.async.commit_group;" ::: "memory");
}
template <int N>
__device__ __forceinline__ void cp_wait() {
    asm volatile("cp.async.wait_group %0;" :: "n"(N) : "memory");
}
__device__ __forceinline__ void ldsm4(uint32_t* r, uint32_t addr) {
    asm volatile("ldmatrix.sync.aligned.m8n8.x4.shared.b16 {%0,%1,%2,%3}, [%4];"
                 : "=r"(r[0]), "=r"(r[1]), "=r"(r[2]), "=r"(r[3]) : "r"(addr));
}
__device__ __forceinline__ void mma16816(float* d, const uint32_t* a, uint32_t b0, uint32_t b1) {
    asm volatile(
        "mma.sync.aligned.m16n8k16.row.col.f32.f16.f16.f32 "
        "{%0,%1,%2,%3}, {%4,%5,%6,%7}, {%8,%9}, {%0,%1,%2,%3};"
        : "+f"(d[0]), "+f"(d[1]), "+f"(d[2]), "+f"(d[3])
        : "r"(a[0]), "r"(a[1]), "r"(a[2]), "r"(a[3]), "r"(b0), "r"(b1));
}

// ---------------- Kernel 1 (fused prep): W fake-quant->fp16  +  X->fp16 ----------------
#define WBLOCKS ((DN * DK / GROUP) / 8)              // 16384
#define XBLOCKS 4096
#define XSTRIDE (XBLOCKS * 256)                      // float4 stride per iteration

__global__ __launch_bounds__(256) void prep_kernel(const float* __restrict__ w,
                                                   const float* __restrict__ x) {
    const int bx = blockIdx.x;
    if (bx < WBLOCKS) {
        // ---- weight fake-quant ----
        const int warp = threadIdx.x >> 5;
        const int lane = threadIdx.x & 31;
        const long g = (long)bx * 8 + warp;          // group over flattened W

        const float4 v4 = ((const float4*)(w + g * GROUP))[lane];
        float v[4] = {v4.x, v4.y, v4.z, v4.w};

        float mn = fminf(fminf(v[0], v[1]), fminf(v[2], v[3]));
        float mx = fmaxf(fmaxf(v[0], v[1]), fmaxf(v[2], v[3]));
#pragma unroll
        for (int o = 16; o > 0; o >>= 1) {
            mn = fminf(mn, __shfl_xor_sync(0xffffffffu, mn, o));
            mx = fmaxf(mx, __shfl_xor_sync(0xffffffffu, mx, o));
        }
        const float rng = mx - mn;
        const bool pass = rng < EPSQ;
        const float scale = rng * (1.0f / 3.0f);
        const float inv = pass ? 1.0f : (1.0f / scale);

        __half h[4];
#pragma unroll
        for (int i = 0; i < 4; i++) {
            float q = rintf((v[i] - mn) * inv);      // half-even like jnp.round
            q = fminf(fmaxf(q, 0.0f), 3.0f);
            float deq = pass ? v[i] : fmaf(q, scale, mn);
            h[i] = __float2half(deq);
        }
        ((uint2*)(g_wq + g * GROUP))[lane] = *(uint2*)h;
    } else {
        // ---- X convert ----
        const size_t base = (size_t)(bx - WBLOCKS) * 256 + threadIdx.x;
        const float4* __restrict__ xp = (const float4*)x;
#pragma unroll
        for (int i = 0; i < 8; i++) {
            const size_t i4 = base + (size_t)i * XSTRIDE;
            float4 v = xp[i4];
            __half h[4];
            h[0] = __float2half(v.x);
            h[1] = __float2half(v.y);
            h[2] = __float2half(v.z);
            h[3] = __float2half(v.w);
            *(uint2*)&g_xh[i4 * 4] = *(uint2*)h;
        }
    }
}

// ---------------- Kernel 2: single-pass fp16 mma.sync GEMM ----------------
// 512 threads, 16 warps in a 4x4 grid; warp tile 32x64.
// SMEM per stage: A 128x64 fp16 (16KB) + B 256x64 fp16 (32KB) = 48KB; 4 stages.
#define A_BYTES (128 * 128)
#define B_BYTES (256 * 128)
#define STAGE_BYTES (A_BYTES + B_BYTES)        // 48KB
#define SM_TOTAL (NBUF * STAGE_BYTES)          // 192KB

__global__ __launch_bounds__(512, 1) void gemm_kernel(
    const float* __restrict__ bias, float* __restrict__ C) {

    extern __shared__ char sm[];
    const uint32_t sbase = smem_u32(sm);

    const int tid = threadIdx.x;
    const int wid = tid >> 5;
    const int lane = tid & 31;
    const int wm = wid & 3;           // 0..3 -> warp rows [wm*32, +32)
    const int wn = wid >> 2;          // 0..3 -> warp cols [wn*64, +64)
    const int bn = blockIdx.x * BN;
    const int bm = blockIdx.y * BM;

    const __half* __restrict__ X = g_xh;
    const __half* __restrict__ W = g_wq;

    // loader mapping: 16B chunks; A: 1024 chunks (2/thread), B: 2048 (4/thread)
    const int lrow = tid >> 3;            // 0..63, advances by 64 (row&7 invariant)
    const int lchk = tid & 7;
    const uint32_t lso = swz128(lrow * 128 + lchk * 16);
    const size_t lgo = (size_t)lrow * DK + lchk * 8;

    auto load_stage = [&](int s, int buf) {
        const int k0 = s * BKE;
        const uint32_t st = sbase + buf * STAGE_BYTES;
#pragma unroll
        for (int it = 0; it < 2; it++) {
            cp_async16(st + lso + it * 64 * 128,
                       X + (size_t)bm * DK + lgo + (size_t)it * 64 * DK + k0);
        }
#pragma unroll
        for (int it = 0; it < 4; it++) {
            cp_async16(st + A_BYTES + lso + it * 64 * 128,
                       W + (size_t)bn * DK + lgo + (size_t)it * 64 * DK + k0);
        }
        cp_commit();
    };

    float accb[2][8][4];
#pragma unroll
    for (int i = 0; i < 2; i++)
#pragma unroll
        for (int j = 0; j < 8; j++)
#pragma unroll
            for (int c = 0; c < 4; c++) accb[i][j][c] = 0.0f;

    // ldmatrix per-lane base byte offsets (unswizzled)
    const uint32_t arow = (uint32_t)(wm * 32 + (lane & 15)) * 128 + (uint32_t)(lane >> 4) * 16;
    const uint32_t brow = (uint32_t)(wn * 64 + (lane & 15)) * 128 + (uint32_t)(lane >> 4) * 16;

    // preload 3 stages
    load_stage(0, 0);
    load_stage(1, 1);
    load_stage(2, 2);

    for (int s = 0; s < NSTAGES; s++) {
        cp_wait<2>();
        __syncthreads();
        if (s + 3 < NSTAGES) load_stage(s + 3, (s + 3) & (NBUF - 1));

        const uint32_t st = sbase + (s & (NBUF - 1)) * STAGE_BYTES;
        const uint32_t sA = st;
        const uint32_t sB = st + A_BYTES;

#pragma unroll
        for (int kk = 0; kk < 4; kk++) {
            uint32_t a[2][4], b[4][4];
#pragma unroll
            for (int nt = 0; nt < 4; nt++)
                ldsm4(b[nt], sB + swz128(brow + nt * 2048 + kk * 32));
#pragma unroll
            for (int mt = 0; mt < 2; mt++)
                ldsm4(a[mt], sA + swz128(arow + mt * 2048 + kk * 32));
#pragma unroll
            for (int mt = 0; mt < 2; mt++)
#pragma unroll
                for (int nt = 0; nt < 4; nt++) {
                    mma16816(accb[mt][nt * 2 + 0], a[mt], b[nt][0], b[nt][2]);
                    mma16816(accb[mt][nt * 2 + 1], a[mt], b[nt][1], b[nt][3]);
                }
        }
        // buffer reuse gated by next iteration's cp_wait + syncthreads
    }

    // ---- epilogue: + bias, float2 stores ----
    const int qr = lane >> 2;           // 0..7
    const int qc = (lane & 3) * 2;      // 0,2,4,6
#pragma unroll
    for (int mt = 0; mt < 2; mt++) {
        const int r0 = bm + wm * 32 + mt * 16 + qr;
#pragma unroll
        for (int n8 = 0; n8 < 8; n8++) {
            const int col = bn + wn * 64 + n8 * 8 + qc;
            const float2 bv = *(const float2*)(bias + col);
            float2 o0, o1;
            o0.x = accb[mt][n8][0] + bv.x;
            o0.y = accb[mt][n8][1] + bv.y;
            o1.x = accb[mt][n8][2] + bv.x;
            o1.y = accb[mt][n8][3] + bv.y;
            *(float2*)(C + (size_t)r0 * DN + col) = o0;
            *(float2*)(C + (size_t)(r0 + 8) * DN + col) = o1;
        }
    }
}

// ---------------------------------------------------------------------------
extern "C" void kernel_launch(void* const* d_in, const int* in_sizes, int n_in,
                              void* d_out, int out_size) {
    const float* x    = (const float*)d_in[0];
    const float* w    = (const float*)d_in[1];
    const float* bias = (const float*)d_in[2];
    float* out = (float*)d_out;

    cudaFuncSetAttribute(gemm_kernel, cudaFuncAttributeMaxDynamicSharedMemorySize, SM_TOTAL);

    prep_kernel<<<WBLOCKS + XBLOCKS, 256>>>(w, x);

    dim3 grid(DN / BN, DM / BM);
    gemm_kernel<<<grid, 512, SM_TOTAL>>>(bias, out);
}

// round 12
// speedup vs baseline: 7.6811x; 1.0044x over previous
#include <cuda_runtime.h>
#include <cuda_fp16.h>
#include <cstdint>

#define DK 4096
#define DN 4096
#define DM 8192
#define GROUP 128
#define EPSQ 1e-8f

#define BM 128
#define BN 128
#define BKE 64                 // K elements per stage (64 fp16 = 128B rows)
#define NSTAGES (DK / BKE)
#define NBUF 3

// ---------------- device scratch (allocation-free rule) ----------------
__device__ __half g_wq [(size_t)DN * DK];   // dequantized weight, fp16
__device__ __half g_xh [(size_t)DM * DK];   // x, fp16

// ---------------- PTX helpers (baseline sm_80+ ISA only) ----------------
__device__ __forceinline__ uint32_t smem_u32(const void* p) {
    uint32_t a;
    asm("{ .reg .u64 t; cvta.to.shared.u64 t, %1; cvt.u32.u64 %0, t; }" : "=r"(a) : "l"(p));
    return a;
}
__device__ __forceinline__ uint32_t swz128(uint32_t off) {
    return off ^ ((off >> 3) & 0x70);
}
__device__ __forceinline__ void cp_async16(uint32_t saddr, const void* gaddr) {
    asm volatile("cp.async.cg.shared.global [%0], [%1], 16;" :: "r"(saddr), "l"(gaddr) : "memory");
}
__device__ __forceinline__ void cp_commit() {
    asm volatile("cp.async.commit_group;" ::: "memory");
}
template <int N>
__device__ __forceinline__ void cp_wait() {
    asm volatile("cp.async.wait_group %0;" :: "n"(N) : "memory");
}
__device__ __forceinline__ void ldsm4(uint32_t* r, uint32_t addr) {
    asm volatile("ldmatrix.sync.aligned.m8n8.x4.shared.b16 {%0,%1,%2,%3}, [%4];"
                 : "=r"(r[0]), "=r"(r[1]), "=r"(r[2]), "=r"(r[3]) : "r"(addr));
}
__device__ __forceinline__ void mma16816(float* d, const uint32_t* a, uint32_t b0, uint32_t b1) {
    asm volatile(
        "mma.sync.aligned.m16n8k16.row.col.f32.f16.f16.f32 "
        "{%0,%1,%2,%3}, {%4,%5,%6,%7}, {%8,%9}, {%0,%1,%2,%3};"
        : "+f"(d[0]), "+f"(d[1]), "+f"(d[2]), "+f"(d[3])
        : "r"(a[0]), "r"(a[1]), "r"(a[2]), "r"(a[3]), "r"(b0), "r"(b1));
}

// ---------------- Kernel 1 (fused prep): W fake-quant->fp16  +  X->fp16 ----------------
#define WBLOCKS ((DN * DK / GROUP) / 8)              // 16384
#define XBLOCKS 4096
#define XSTRIDE (XBLOCKS * 256)                      // float4 stride per iteration

__global__ __launch_bounds__(256) void prep_kernel(const float* __restrict__ w,
                                                   const float* __restrict__ x) {
    const int bx = blockIdx.x;
    if (bx < WBLOCKS) {
        // ---- weight fake-quant ----
        const int warp = threadIdx.x >> 5;
        const int lane = threadIdx.x & 31;
        const long g = (long)bx * 8 + warp;          // group over flattened W

        const float4 v4 = ((const float4*)(w + g * GROUP))[lane];
        float v[4] = {v4.x, v4.y, v4.z, v4.w};

        float mn = fminf(fminf(v[0], v[1]), fminf(v[2], v[3]));
        float mx = fmaxf(fmaxf(v[0], v[1]), fmaxf(v[2], v[3]));
#pragma unroll
        for (int o = 16; o > 0; o >>= 1) {
            mn = fminf(mn, __shfl_xor_sync(0xffffffffu, mn, o));
            mx = fmaxf(mx, __shfl_xor_sync(0xffffffffu, mx, o));
        }
        const float rng = mx - mn;
        const bool pass = rng < EPSQ;
        const float scale = rng * (1.0f / 3.0f);
        const float inv = pass ? 1.0f : (1.0f / scale);

        __half h[4];
#pragma unroll
        for (int i = 0; i < 4; i++) {
            float q = rintf((v[i] - mn) * inv);      // half-even like jnp.round
            q = fminf(fmaxf(q, 0.0f), 3.0f);
            float deq = pass ? v[i] : fmaf(q, scale, mn);
            h[i] = __float2half(deq);
        }
        ((uint2*)(g_wq + g * GROUP))[lane] = *(uint2*)h;
    } else {
        // ---- X convert ----
        const size_t base = (size_t)(bx - WBLOCKS) * 256 + threadIdx.x;
        const float4* __restrict__ xp = (const float4*)x;
#pragma unroll
        for (int i = 0; i < 8; i++) {
            const size_t i4 = base + (size_t)i * XSTRIDE;
            float4 v = xp[i4];
            __half h[4];
            h[0] = __float2half(v.x);
            h[1] = __float2half(v.y);
            h[2] = __float2half(v.z);
            h[3] = __float2half(v.w);
            *(uint2*)&g_xh[i4 * 4] = *(uint2*)h;
        }
    }
}

// ---------------- Kernel 2: single-pass fp16 mma.sync GEMM ----------------
// 128x128 CTA tile, 256 threads (8 warps, 4x2 grid of 32x64 warp tiles).
// SMEM per stage: A 16KB + B 16KB = 32KB; 3 stages = 96KB -> 2 CTAs per SM.
// The two co-resident CTAs hit their stage barriers at uncorrelated times,
// so one CTA's MMA stream covers the other's barrier/ldsm bursts.
#define A_BYTES (128 * 128)
#define B_BYTES (128 * 128)
#define STAGE_BYTES (A_BYTES + B_BYTES)        // 32KB
#define SM_TOTAL (NBUF * STAGE_BYTES)          // 96KB

__global__ __launch_bounds__(256, 2) void gemm_kernel(
    const float* __restrict__ bias, float* __restrict__ C) {

    extern __shared__ char sm[];
    const uint32_t sbase = smem_u32(sm);

    const int tid = threadIdx.x;
    const int wid = tid >> 5;
    const int lane = tid & 31;
    const int wm = wid & 3;           // 0..3 -> warp rows [wm*32, +32)
    const int wn = wid >> 2;          // 0..1 -> warp cols [wn*64, +64)
    const int bn = blockIdx.x * BN;
    const int bm = blockIdx.y * BM;

    const __half* __restrict__ X = g_xh;
    const __half* __restrict__ W = g_wq;

    // loader mapping: 16B chunks; A: 1024 chunks (4/thread), B: 1024 (4/thread)
    const int lrow = tid >> 3;            // 0..31, advances by 32 (row&7 invariant)
    const int lchk = tid & 7;
    const uint32_t lso = swz128(lrow * 128 + lchk * 16);
    const size_t lgo = (size_t)lrow * DK + lchk * 8;

    auto load_stage = [&](int s, int buf) {
        const int k0 = s * BKE;
        const uint32_t st = sbase + buf * STAGE_BYTES;
#pragma unroll
        for (int it = 0; it < 4; it++) {
            cp_async16(st + lso + it * 32 * 128,
                       X + (size_t)bm * DK + lgo + (size_t)it * 32 * DK + k0);
        }
#pragma unroll
        for (int it = 0; it < 4; it++) {
            cp_async16(st + A_BYTES + lso + it * 32 * 128,
                       W + (size_t)bn * DK + lgo + (size_t)it * 32 * DK + k0);
        }
        cp_commit();
    };

    float accb[2][8][4];
#pragma unroll
    for (int i = 0; i < 2; i++)
#pragma unroll
        for (int j = 0; j < 8; j++)
#pragma unroll
            for (int c = 0; c < 4; c++) accb[i][j][c] = 0.0f;

    // ldmatrix per-lane base byte offsets (unswizzled)
    const uint32_t arow = (uint32_t)(wm * 32 + (lane & 15)) * 128 + (uint32_t)(lane >> 4) * 16;
    const uint32_t brow = (uint32_t)(wn * 64 + (lane & 15)) * 128 + (uint32_t)(lane >> 4) * 16;

    // preload 2 stages
    load_stage(0, 0);
    load_stage(1, 1);

    for (int s = 0; s < NSTAGES; s++) {
        cp_wait<1>();                 // stage s resident
        __syncthreads();              // all warps done with stage s-1's buffer
        if (s + 2 < NSTAGES)          // overwrite s-1's buffer with s+2
            load_stage(s + 2, (s + 2) % NBUF);

        const uint32_t st = sbase + (s % NBUF) * STAGE_BYTES;
        const uint32_t sA = st;
        const uint32_t sB = st + A_BYTES;

#pragma unroll
        for (int kk = 0; kk < 4; kk++) {
            uint32_t a[2][4], b[4][4];
#pragma unroll
            for (int nt = 0; nt < 4; nt++)
                ldsm4(b[nt], sB + swz128(brow + nt * 2048 + kk * 32));
#pragma unroll
            for (int mt = 0; mt < 2; mt++)
                ldsm4(a[mt], sA + swz128(arow + mt * 2048 + kk * 32));
#pragma unroll
            for (int mt = 0; mt < 2; mt++)
#pragma unroll
                for (int nt = 0; nt < 4; nt++) {
                    mma16816(accb[mt][nt * 2 + 0], a[mt], b[nt][0], b[nt][2]);
                    mma16816(accb[mt][nt * 2 + 1], a[mt], b[nt][1], b[nt][3]);
                }
        }
        // buffer reuse gated by next iteration's cp_wait + syncthreads
    }

    // ---- epilogue: + bias, float2 stores ----
    const int qr = lane >> 2;           // 0..7
    const int qc = (lane & 3) * 2;      // 0,2,4,6
#pragma unroll
    for (int mt = 0; mt < 2; mt++) {
        const int r0 = bm + wm * 32 + mt * 16 + qr;
#pragma unroll
        for (int n8 = 0; n8 < 8; n8++) {
            const int col = bn + wn * 64 + n8 * 8 + qc;
            const float2 bv = *(const float2*)(bias + col);
            float2 o0, o1;
            o0.x = accb[mt][n8][0] + bv.x;
            o0.y = accb[mt][n8][1] + bv.y;
            o1.x = accb[mt][n8][2] + bv.x;
            o1.y = accb[mt][n8][3] + bv.y;
            *(float2*)(C + (size_t)r0 * DN + col) = o0;
            *(float2*)(C + (size_t)(r0 + 8) * DN + col) = o1;
        }
    }
}

// ---------------------------------------------------------------------------
extern "C" void kernel_launch(void* const* d_in, const int* in_sizes, int n_in,
                              void* d_out, int out_size) {
    const float* x    = (const float*)d_in[0];
    const float* w    = (const float*)d_in[1];
    const float* bias = (const float*)d_in[2];
    float* out = (float*)d_out;

    cudaFuncSetAttribute(gemm_kernel, cudaFuncAttributeMaxDynamicSharedMemorySize, SM_TOTAL);

    prep_kernel<<<WBLOCKS + XBLOCKS, 256>>>(w, x);

    dim3 grid(DN / BN, DM / BM);
    gemm_kernel<<<grid, 256, SM_TOTAL>>>(bias, out);
}

// round 13
// speedup vs baseline: 7.8301x; 1.0194x over previous
#include <cuda_runtime.h>
#include <cuda_fp16.h>
#include <cstdint>

#define DK 4096
#define DN 4096
#define DM 8192
#define GROUP 128
#define EPSQ 1e-8f

#define BM 128
#define BN 256
#define BKE 128                // K elements per stage (two 64-col SW128 sub-tiles)
#define NSTAGES (DK / BKE)     // 32
#define NBUF 2

// ---------------- device scratch (allocation-free rule) ----------------
__device__ __half g_wq [(size_t)DN * DK];   // dequantized weight, fp16
__device__ __half g_xh [(size_t)DM * DK];   // x, fp16

// ---------------- PTX helpers (baseline sm_80+ ISA only) ----------------
__device__ __forceinline__ uint32_t smem_u32(const void* p) {
    uint32_t a;
    asm("{ .reg .u64 t; cvta.to.shared.u64 t, %1; cvt.u32.u64 %0, t; }" : "=r"(a) : "l"(p));
    return a;
}
__device__ __forceinline__ uint32_t swz128(uint32_t off) {
    return off ^ ((off >> 3) & 0x70);
}
__device__ __forceinline__ void cp_async16(uint32_t saddr, const void* gaddr) {
    asm volatile("cp.async.cg.shared.global [%0], [%1], 16;" :: "r"(saddr), "l"(gaddr) : "memory");
}
__device__ __forceinline__ void cp_commit() {
    asm volatile("cp.async.commit_group;" ::: "memory");
}
template <int N>
__device__ __forceinline__ void cp_wait() {
    asm volatile("cp.async.wait_group %0;" :: "n"(N) : "memory");
}
__device__ __forceinline__ void ldsm4(uint32_t* r, uint32_t addr) {
    asm volatile("ldmatrix.sync.aligned.m8n8.x4.shared.b16 {%0,%1,%2,%3}, [%4];"
                 : "=r"(r[0]), "=r"(r[1]), "=r"(r[2]), "=r"(r[3]) : "r"(addr));
}
__device__ __forceinline__ void mma16816(float* d, const uint32_t* a, uint32_t b0, uint32_t b1) {
    asm volatile(
        "mma.sync.aligned.m16n8k16.row.col.f32.f16.f16.f32 "
        "{%0,%1,%2,%3}, {%4,%5,%6,%7}, {%8,%9}, {%0,%1,%2,%3};"
        : "+f"(d[0]), "+f"(d[1]), "+f"(d[2]), "+f"(d[3])
        : "r"(a[0]), "r"(a[1]), "r"(a[2]), "r"(a[3]), "r"(b0), "r"(b1));
}

// ---------------- Kernel 1 (fused prep): W fake-quant->fp16  +  X->fp16 ----------------
#define WBLOCKS ((DN * DK / GROUP) / 8)              // 16384
#define XBLOCKS 4096
#define XSTRIDE (XBLOCKS * 256)                      // float4 stride per iteration

__global__ __launch_bounds__(256) void prep_kernel(const float* __restrict__ w,
                                                   const float* __restrict__ x) {
    const int bx = blockIdx.x;
    if (bx < WBLOCKS) {
        // ---- weight fake-quant ----
        const int warp = threadIdx.x >> 5;
        const int lane = threadIdx.x & 31;
        const long g = (long)bx * 8 + warp;          // group over flattened W

        const float4 v4 = ((const float4*)(w + g * GROUP))[lane];
        float v[4] = {v4.x, v4.y, v4.z, v4.w};

        float mn = fminf(fminf(v[0], v[1]), fminf(v[2], v[3]));
        float mx = fmaxf(fmaxf(v[0], v[1]), fmaxf(v[2], v[3]));
#pragma unroll
        for (int o = 16; o > 0; o >>= 1) {
            mn = fminf(mn, __shfl_xor_sync(0xffffffffu, mn, o));
            mx = fmaxf(mx, __shfl_xor_sync(0xffffffffu, mx, o));
        }
        const float rng = mx - mn;
        const bool pass = rng < EPSQ;
        const float scale = rng * (1.0f / 3.0f);
        const float inv = pass ? 1.0f : (1.0f / scale);

        __half h[4];
#pragma unroll
        for (int i = 0; i < 4; i++) {
            float q = rintf((v[i] - mn) * inv);      // half-even like jnp.round
            q = fminf(fmaxf(q, 0.0f), 3.0f);
            float deq = pass ? v[i] : fmaf(q, scale, mn);
            h[i] = __float2half(deq);
        }
        ((uint2*)(g_wq + g * GROUP))[lane] = *(uint2*)h;
    } else {
        // ---- X convert ----
        const size_t base = (size_t)(bx - WBLOCKS) * 256 + threadIdx.x;
        const float4* __restrict__ xp = (const float4*)x;
#pragma unroll
        for (int i = 0; i < 8; i++) {
            const size_t i4 = base + (size_t)i * XSTRIDE;
            float4 v = xp[i4];
            __half h[4];
            h[0] = __float2half(v.x);
            h[1] = __float2half(v.y);
            h[2] = __float2half(v.z);
            h[3] = __float2half(v.w);
            *(uint2*)&g_xh[i4 * 4] = *(uint2*)h;
        }
    }
}

// ---------------- Kernel 2: single-pass fp16 mma.sync GEMM ----------------
// 128x256 CTA tile, 512 threads (16 warps, 4x4 grid of 32x64 warp tiles).
// BKE=128: each stage holds TWO 64-col SW128 sub-tiles per operand.
// Stage: A0(16K) A1(16K) B0(32K) B1(32K) = 96KB; NBUF=2 -> 192KB smem.
// Half the stage barriers of the BKE=64 design: 8 k-steps of MMA per barrier.
#define A_HALF (128 * 128)                  // 16KB: 128 rows x 128B
#define B_HALF (256 * 128)                  // 32KB
#define SA0 0
#define SA1 A_HALF
#define SB0 (2 * A_HALF)
#define SB1 (2 * A_HALF + B_HALF)
#define STAGE_BYTES (2 * A_HALF + 2 * B_HALF)   // 96KB
#define SM_TOTAL (NBUF * STAGE_BYTES)           // 192KB

__global__ __launch_bounds__(512, 1) void gemm_kernel(
    const float* __restrict__ bias, float* __restrict__ C) {

    extern __shared__ char sm[];
    const uint32_t sbase = smem_u32(sm);

    const int tid = threadIdx.x;
    const int wid = tid >> 5;
    const int lane = tid & 31;
    const int wm = wid & 3;           // 0..3 -> warp rows [wm*32, +32)
    const int wn = wid >> 2;          // 0..3 -> warp cols [wn*64, +64)
    const int bn = blockIdx.x * BN;
    const int bm = blockIdx.y * BM;

    const __half* __restrict__ X = g_xh;
    const __half* __restrict__ W = g_wq;

    // loader mapping: 16B chunks within a 64-col sub-tile; row=idx>>3, chunk=idx&7
    const int lrow = tid >> 3;            // 0..63, advances by 64 (row&7 invariant)
    const int lchk = tid & 7;
    const uint32_t lso = swz128(lrow * 128 + lchk * 16);
    const size_t lgo = (size_t)lrow * DK + lchk * 8;

    auto load_stage = [&](int s, int buf) {
        const uint32_t st = sbase + buf * STAGE_BYTES;
#pragma unroll
        for (int h = 0; h < 2; h++) {
            const int k0 = s * BKE + h * 64;
            // A sub-tile: 128 rows -> 1024 chunks -> 2 per thread
#pragma unroll
            for (int it = 0; it < 2; it++) {
                cp_async16(st + SA0 + h * A_HALF + lso + it * 64 * 128,
                           X + (size_t)bm * DK + lgo + (size_t)it * 64 * DK + k0);
            }
            // B sub-tile: 256 rows -> 2048 chunks -> 4 per thread
#pragma unroll
            for (int it = 0; it < 4; it++) {
                cp_async16(st + SB0 + h * B_HALF + lso + it * 64 * 128,
                           W + (size_t)bn * DK + lgo + (size_t)it * 64 * DK + k0);
            }
        }
        cp_commit();
    };

    float accb[2][8][4];
#pragma unroll
    for (int i = 0; i < 2; i++)
#pragma unroll
        for (int j = 0; j < 8; j++)
#pragma unroll
            for (int c = 0; c < 4; c++) accb[i][j][c] = 0.0f;

    // ldmatrix per-lane base byte offsets (unswizzled, within a sub-tile)
    const uint32_t arow = (uint32_t)(wm * 32 + (lane & 15)) * 128 + (uint32_t)(lane >> 4) * 16;
    const uint32_t brow = (uint32_t)(wn * 64 + (lane & 15)) * 128 + (uint32_t)(lane >> 4) * 16;

    load_stage(0, 0);

    for (int s = 0; s < NSTAGES; s++) {
        cp_wait<0>();                 // stage s fully resident
        __syncthreads();              // all warps done with stage s-1's buffer
        if (s + 1 < NSTAGES)
            load_stage(s + 1, (s + 1) & 1);   // overwrite s-1's buffer

        const uint32_t st = sbase + (s & 1) * STAGE_BYTES;

#pragma unroll
        for (int kk = 0; kk < 8; kk++) {
            const int half = kk >> 2;
            const int ksub = kk & 3;
            const uint32_t sA = st + SA0 + half * A_HALF;
            const uint32_t sB = st + SB0 + half * B_HALF;

            uint32_t a[2][4], b[4][4];
#pragma unroll
            for (int nt = 0; nt < 4; nt++)
                ldsm4(b[nt], sB + swz128(brow + nt * 2048 + ksub * 32));
#pragma unroll
            for (int mt = 0; mt < 2; mt++)
                ldsm4(a[mt], sA + swz128(arow + mt * 2048 + ksub * 32));
#pragma unroll
            for (int mt = 0; mt < 2; mt++)
#pragma unroll
                for (int nt = 0; nt < 4; nt++) {
                    mma16816(accb[mt][nt * 2 + 0], a[mt], b[nt][0], b[nt][2]);
                    mma16816(accb[mt][nt * 2 + 1], a[mt], b[nt][1], b[nt][3]);
                }
        }
        // buffer reuse gated by next iteration's cp_wait + syncthreads
    }

    // ---- epilogue: + bias, float2 stores ----
    const int qr = lane >> 2;           // 0..7
    const int qc = (lane & 3) * 2;      // 0,2,4,6
#pragma unroll
    for (int mt = 0; mt < 2; mt++) {
        const int r0 = bm + wm * 32 + mt * 16 + qr;
#pragma unroll
        for (int n8 = 0; n8 < 8; n8++) {
            const int col = bn + wn * 64 + n8 * 8 + qc;
            const float2 bv = *(const float2*)(bias + col);
            float2 o0, o1;
            o0.x = accb[mt][n8][0] + bv.x;
            o0.y = accb[mt][n8][1] + bv.y;
            o1.x = accb[mt][n8][2] + bv.x;
            o1.y = accb[mt][n8][3] + bv.y;
            *(float2*)(C + (size_t)r0 * DN + col) = o0;
            *(float2*)(C + (size_t)(r0 + 8) * DN + col) = o1;
        }
    }
}

// ---------------------------------------------------------------------------
extern "C" void kernel_launch(void* const* d_in, const int* in_sizes, int n_in,
                              void* d_out, int out_size) {
    const float* x    = (const float*)d_in[0];
    const float* w    = (const float*)d_in[1];
    const float* bias = (const float*)d_in[2];
    float* out = (float*)d_out;

    cudaFuncSetAttribute(gemm_kernel, cudaFuncAttributeMaxDynamicSharedMemorySize, SM_TOTAL);

    prep_kernel<<<WBLOCKS + XBLOCKS, 256>>>(w, x);

    dim3 grid(DN / BN, DM / BM);
    gemm_kernel<<<grid, 512, SM_TOTAL>>>(bias, out);
}